// round 2
// baseline (speedup 1.0000x reference)
#include <cuda_runtime.h>

#define BH      32
#define D       16
#define DV      64
#define CS      256
#define NC      16
#define NCHUNK  512
#define NPAIR   136

// state layout (floats) per chunk
#define OFF_KSUM  0
#define OFF_K2    16
#define OFF_VSUM  152
#define OFF_KVLIN 216
#define OFF_KVQ   1240
#define S_FLOATS  9944   // 16 + 136 + 64 + 1024 + 8704

__device__ __align__(16) float g_state[(size_t)NCHUNK * S_FLOATS];

__device__ __forceinline__ void fma4(float4& a, float c, const float4 v) {
    a.x = fmaf(c, v.x, a.x);
    a.y = fmaf(c, v.y, a.y);
    a.z = fmaf(c, v.z, a.z);
    a.w = fmaf(c, v.w, a.w);
}

// ---------------------------------------------------------------------------
// Pass 1: per-chunk states.  512 CTAs x 256 threads.
// ---------------------------------------------------------------------------
__global__ __launch_bounds__(256) void build_kernel(const float* __restrict__ kg,
                                                    const float* __restrict__ vg) {
    extern __shared__ float smem[];
    float* sv = smem;               // CS*DV floats
    float* sk = smem + CS * DV;     // CS*D floats
    const int cg  = blockIdx.x;
    const int tid = threadIdx.x;

    float4* sv4 = (float4*)sv;
    float4* sk4 = (float4*)sk;
    const float4* gv4 = (const float4*)(vg + (size_t)cg * CS * DV);
    const float4* gk4 = (const float4*)(kg + (size_t)cg * CS * D);
#pragma unroll
    for (int i = 0; i < 16; ++i) sv4[tid + 256 * i] = gv4[tid + 256 * i];
#pragma unroll
    for (int i = 0; i < 4; ++i)  sk4[tid + 256 * i] = gk4[tid + 256 * i];
    __syncthreads();

    float* st = g_state + (size_t)cg * S_FLOATS;

    if (tid < NPAIR) {
        // pair (d,e), d<=e, enumerated (0,0..15),(1,1..15),...
        int d = 0, pp = tid;
        while (pp >= D - d) { pp -= (D - d); ++d; }
        const int e = d + pp;
        const float w = (e == d) ? 0.5f : 1.0f;   // fold the 0.5 quad factor here

        float4 acc[16];
#pragma unroll
        for (int f = 0; f < 16; ++f) acc[f] = make_float4(0.f, 0.f, 0.f, 0.f);
        float acc2 = 0.f;

        for (int c = 0; c < CS; ++c) {
            const float coeff = sk[c * D + d] * sk[c * D + e];
            acc2 += coeff;
            const float4* vr = sv4 + c * 16;
#pragma unroll
            for (int f = 0; f < 16; ++f) fma4(acc[f], coeff, vr[f]);
        }

        float4* dst = (float4*)(st + OFF_KVQ + tid * DV);
#pragma unroll
        for (int f = 0; f < 16; ++f) {
            acc[f].x *= w; acc[f].y *= w; acc[f].z *= w; acc[f].w *= w;
            dst[f] = acc[f];
        }
        st[OFF_K2 + tid] = acc2 * w;
    } else {
        const int t = tid - NPAIR;    // 0..119
        for (int idx = t; idx < D * DV; idx += 256 - NPAIR) {
            const int d = idx >> 6, f = idx & 63;
            float a = 0.f;
            for (int c = 0; c < CS; ++c) a = fmaf(sk[c * D + d], sv[c * DV + f], a);
            st[OFF_KVLIN + idx] = a;
        }
        if (t < D) {
            float a = 0.f;
            for (int c = 0; c < CS; ++c) a += sk[c * D + t];
            st[OFF_KSUM + t] = a;
        } else if (t < D + DV) {
            const int f = t - D;
            float a = 0.f;
            for (int c = 0; c < CS; ++c) a += sv[c * DV + f];
            st[OFF_VSUM + f] = a;
        }
    }
}

// ---------------------------------------------------------------------------
// Pass 2: in-place EXCLUSIVE prefix over the 16 chunks of each (b,h).
// grid (32, 4) x 256 threads; MLP=16 per element.
// ---------------------------------------------------------------------------
__global__ void prefix_kernel() {
    const int bh = blockIdx.x;
    const int stride = gridDim.y * blockDim.x;
    for (int i = blockIdx.y * blockDim.x + threadIdx.x; i < S_FLOATS; i += stride) {
        float* p = g_state + (size_t)bh * NC * S_FLOATS + i;
        float vals[NC];
#pragma unroll
        for (int c = 0; c < NC; ++c) vals[c] = p[(size_t)c * S_FLOATS];
        float run = 0.f;
#pragma unroll
        for (int c = 0; c < NC; ++c) {
            const float t = vals[c];
            p[(size_t)c * S_FLOATS] = run;
            run += t;
        }
    }
}

// ---------------------------------------------------------------------------
// Pass 3: intra-chunk phi-attention + apply exclusive state, divide by z.
// 512 CTAs x 256 threads (thread = query row).
// ---------------------------------------------------------------------------
__global__ __launch_bounds__(256) void main_kernel(const float* __restrict__ qg,
                                                   const float* __restrict__ kg,
                                                   const float* __restrict__ vg,
                                                   float* __restrict__ outg) {
    extern __shared__ float smem[];
    float* sv     = smem;                 // CS*DV   = 16384 f
    float* sstate = sv + CS * DV;         // S_FLOATS=  9944 f
    float* sk     = sstate + S_FLOATS;    // CS*D    =  4096 f
    float* qs     = sk + CS * D;          // CS*17   =  4352 f (padded, thread-private rows)
    const int cg  = blockIdx.x;
    const int nc  = cg & (NC - 1);
    const int tid = threadIdx.x;

    float4* sv4 = (float4*)sv;
    float4* sk4 = (float4*)sk;
    float4* ss4 = (float4*)sstate;
    const float4* gv4 = (const float4*)(vg + (size_t)cg * CS * DV);
    const float4* gk4 = (const float4*)(kg + (size_t)cg * CS * D);
    const float4* gs4 = (const float4*)(g_state + (size_t)cg * S_FLOATS);
#pragma unroll
    for (int i = 0; i < 16; ++i) sv4[tid + 256 * i] = gv4[tid + 256 * i];
#pragma unroll
    for (int i = 0; i < 4; ++i)  sk4[tid + 256 * i] = gk4[tid + 256 * i];
    for (int i = tid; i < S_FLOATS / 4; i += 256) ss4[i] = gs4[i];

    float qreg[16];
    {
        const float4* gq4 = (const float4*)(qg + (size_t)cg * CS * D + (size_t)tid * D);
#pragma unroll
        for (int i = 0; i < 4; ++i) {
            float4 t = gq4[i];                      // q * d^-0.5
            qreg[4 * i + 0] = 0.25f * t.x;
            qreg[4 * i + 1] = 0.25f * t.y;
            qreg[4 * i + 2] = 0.25f * t.z;
            qreg[4 * i + 3] = 0.25f * t.w;
        }
        float* qrow = qs + tid * 17;
#pragma unroll
        for (int i = 0; i < 16; ++i) qrow[i] = qreg[i];
    }
    __syncthreads();

    float4 o4[16];
#pragma unroll
    for (int f = 0; f < 16; ++f) o4[f] = make_float4(0.f, 0.f, 0.f, 0.f);
    float z = 0.f;

    // ---- intra-chunk causal phi-attention (triangular per warp) ----
    const int c    = tid;
    const int jmax = ((c >> 5) + 1) << 5;
#pragma unroll 2
    for (int j = 0; j < jmax; ++j) {
        const float4* kr = sk4 + j * 4;
        float s0 = 0.f, s1 = 0.f;
        {
            float4 kk = kr[0];
            s0 = fmaf(qreg[0], kk.x, s0); s0 = fmaf(qreg[1], kk.y, s0);
            s0 = fmaf(qreg[2], kk.z, s0); s0 = fmaf(qreg[3], kk.w, s0);
            kk = kr[1];
            s0 = fmaf(qreg[4], kk.x, s0); s0 = fmaf(qreg[5], kk.y, s0);
            s0 = fmaf(qreg[6], kk.z, s0); s0 = fmaf(qreg[7], kk.w, s0);
            kk = kr[2];
            s1 = fmaf(qreg[8], kk.x, s1); s1 = fmaf(qreg[9], kk.y, s1);
            s1 = fmaf(qreg[10], kk.z, s1); s1 = fmaf(qreg[11], kk.w, s1);
            kk = kr[3];
            s1 = fmaf(qreg[12], kk.x, s1); s1 = fmaf(qreg[13], kk.y, s1);
            s1 = fmaf(qreg[14], kk.z, s1); s1 = fmaf(qreg[15], kk.w, s1);
        }
        const float s = s0 + s1;
        float phi = fmaf(0.5f * s, s, s) + 1.0f;   // 1 + s + 0.5 s^2
        phi = (j <= c) ? phi : 0.f;
        z += phi;
        const float4* vr = sv4 + j * 16;
#pragma unroll
        for (int f = 0; f < 16; ++f) fma4(o4[f], phi, vr[f]);
    }

    // ---- inter-chunk quadratic state (136 symmetric pairs, pre-weighted) ----
    {
        const float*  sk2 = sstate + OFF_K2;
        const float4* kvq = (const float4*)(sstate + OFF_KVQ);
        const float*  qrow = qs + c * 17;
        int d = 0, e = 0;
#pragma unroll 2
        for (int p = 0; p < NPAIR; ++p) {
            const float coeff = qrow[d] * qrow[e];
            z = fmaf(coeff, sk2[p], z);
            const float4* r = kvq + p * 16;
#pragma unroll
            for (int f = 0; f < 16; ++f) fma4(o4[f], coeff, r[f]);
            if (++e == D) { ++d; e = d; }
        }
    }

    // ---- inter-chunk linear state ----
    {
        const float*  ksum = sstate + OFF_KSUM;
        const float4* kvl  = (const float4*)(sstate + OFF_KVLIN);
#pragma unroll
        for (int d2 = 0; d2 < D; ++d2) {
            const float qd = qreg[d2];
            z = fmaf(qd, ksum[d2], z);
            const float4* r = kvl + d2 * 16;
#pragma unroll
            for (int f = 0; f < 16; ++f) fma4(o4[f], qd, r[f]);
        }
    }

    // ---- zeroth-order inter terms + normalize ----
    z += (float)(nc * CS);
    const float inv = 1.0f / (z + 1e-6f);
    const float4* vsum4 = (const float4*)(sstate + OFF_VSUM);
    float4* out4 = (float4*)(outg + (size_t)cg * CS * DV + (size_t)c * DV);
#pragma unroll
    for (int f = 0; f < 16; ++f) {
        const float4 vs = vsum4[f];
        float4 r;
        r.x = (o4[f].x + vs.x) * inv;
        r.y = (o4[f].y + vs.y) * inv;
        r.z = (o4[f].z + vs.z) * inv;
        r.w = (o4[f].w + vs.w) * inv;
        out4[f] = r;
    }
}

// ---------------------------------------------------------------------------
extern "C" void kernel_launch(void* const* d_in, const int* in_sizes, int n_in,
                              void* d_out, int out_size) {
    (void)in_sizes; (void)n_in; (void)out_size;
    const float* q = (const float*)d_in[0];
    const float* k = (const float*)d_in[1];
    const float* v = (const float*)d_in[2];
    float* out = (float*)d_out;

    const int SMEM_BUILD = (CS * DV + CS * D) * 4;                        // 81920 B
    const int SMEM_MAIN  = (CS * DV + S_FLOATS + CS * D + CS * 17) * 4;   // 139104 B

    cudaFuncSetAttribute(build_kernel, cudaFuncAttributeMaxDynamicSharedMemorySize, SMEM_BUILD);
    cudaFuncSetAttribute(main_kernel,  cudaFuncAttributeMaxDynamicSharedMemorySize, SMEM_MAIN);

    build_kernel<<<NCHUNK, 256, SMEM_BUILD>>>(k, v);
    prefix_kernel<<<dim3(BH, 4), 256>>>();
    main_kernel<<<NCHUNK, 256, SMEM_MAIN>>>(q, k, v, out);
}